// round 9
// baseline (speedup 1.0000x reference)
#include <cuda_runtime.h>
#include <cstddef>

#define BB 8
#define MM 8192
#define DD 256
#define HOPS 3

// Scratch (allocation-free __device__ globals)
__device__ float g_o[BB * DD];        // cumulative sum of o_k across hops (u = q + g_o)
__device__ float g_logits[BB * MM];
__device__ float g_pmax[BB * 128];    // per-block softmax partial max   (128 blocks per b)
__device__ float g_psum[BB * 128];    // per-block partial sum of exp(l - pmax)
__device__ float g_bmax[BB];
__device__ float g_binv[BB];          // 1 / sum_exp

// ---------------------------------------------------------------------------
// K0: zero the cumulative o accumulator
// ---------------------------------------------------------------------------
__global__ void k_init() {
    g_o[blockIdx.x * 256 + threadIdx.x] = 0.0f;   // 8 blocks x 256
}

// ---------------------------------------------------------------------------
// K1: logits[b,m] = gp[b,m] * dot(ms[b,m,:], q[b,:] + g_o[b,:])
//     + per-block softmax stats (max, sum-exp) into g_pmax/g_psum.
// warp-per-row-group: warp reads 8 consecutive 1KB rows (contiguous 8KB
// stream per warp) — the measured-fast pattern (~6.4 TB/s).
// ---------------------------------------------------------------------------
__global__ void __launch_bounds__(256)
k_logits(const float* __restrict__ ms,
         const float* __restrict__ q,
         const float* __restrict__ gp,
         float* __restrict__ out_logits /* null unless last hop */) {
    const int ROWS = 64;
    int row0 = blockIdx.x * ROWS;
    int b = row0 >> 13;                    // / 8192 ; 64 | 8192 -> no straddle
    int lane = threadIdx.x & 31;
    int warp = threadIdx.x >> 5;

    __shared__ float su[DD];
    __shared__ float srow[ROWS];
    su[threadIdx.x] = q[b * DD + threadIdx.x] + g_o[b * DD + threadIdx.x];
    __syncthreads();

    float4 ub0 = reinterpret_cast<const float4*>(su)[lane];
    float4 ub1 = reinterpret_cast<const float4*>(su)[lane + 32];

    int r0 = row0 + warp * 8;
#pragma unroll
    for (int i = 0; i < 8; i++) {
        int row = r0 + i;
        const float4* rp = reinterpret_cast<const float4*>(ms + (size_t)row * DD);
        float4 a0 = rp[lane];
        float4 a1 = rp[lane + 32];
        float s = a0.x * ub0.x + a0.y * ub0.y + a0.z * ub0.z + a0.w * ub0.w
                + a1.x * ub1.x + a1.y * ub1.y + a1.z * ub1.z + a1.w * ub1.w;
#pragma unroll
        for (int off = 16; off; off >>= 1)
            s += __shfl_xor_sync(0xffffffffu, s, off);
        if (lane == 0) {
            float v = s * gp[row];
            g_logits[row] = v;
            srow[warp * 8 + i] = v;
            if (out_logits) out_logits[row] = v;
        }
    }
    __syncthreads();

    // Block-local softmax stats over the 64 logits (warp 0 only)
    if (warp == 0) {
        float v0 = srow[lane];
        float v1 = srow[lane + 32];
        float m = fmaxf(v0, v1);
#pragma unroll
        for (int off = 16; off; off >>= 1)
            m = fmaxf(m, __shfl_xor_sync(0xffffffffu, m, off));
        float s = __expf(v0 - m) + __expf(v1 - m);
#pragma unroll
        for (int off = 16; off; off >>= 1)
            s += __shfl_xor_sync(0xffffffffu, s, off);
        if (lane == 0) {
            g_pmax[blockIdx.x] = m;    // blocks within b are contiguous
            g_psum[blockIdx.x] = s;
        }
    }
}

// ---------------------------------------------------------------------------
// K2: merge 128 partial (max,sum) pairs per b -> (bmax, 1/sum). 1 CTA, 8 warps.
// ---------------------------------------------------------------------------
__global__ void k_combine() {
    int b = threadIdx.x >> 5;
    int lane = threadIdx.x & 31;
    float m = -1e30f, s = 0.0f;
#pragma unroll
    for (int i = 0; i < 4; i++) {
        int idx = b * 128 + i * 32 + lane;
        float pm = g_pmax[idx], ps = g_psum[idx];
        float nm = fmaxf(m, pm);
        s = s * __expf(m - nm) + ps * __expf(pm - nm);
        m = nm;
    }
#pragma unroll
    for (int off = 16; off; off >>= 1) {
        float om = __shfl_xor_sync(0xffffffffu, m, off);
        float os = __shfl_xor_sync(0xffffffffu, s, off);
        float nm = fmaxf(m, om);
        s = s * __expf(m - nm) + os * __expf(om - nm);
        m = nm;
    }
    if (lane == 0) {
        g_bmax[b] = m;
        g_binv[b] = 1.0f / s;
    }
}

// ---------------------------------------------------------------------------
// K3: o[b,:] += sum_m softmax(l)[m] * gp[m] * ms[b,m,:]
// SAME memory pattern as k_logits: warp w streams 8 consecutive rows
// (contiguous 8KB), lane accumulates two weighted float4s covering its
// columns. Cross-warp combine in smem, 64 threads finish with atomics.
// ---------------------------------------------------------------------------
__global__ void __launch_bounds__(256)
k_ok(const float* __restrict__ ms, const float* __restrict__ gp) {
    const int CHUNK = 64;
    int row0 = blockIdx.x * CHUNK;
    int b = row0 >> 13;
    int lane = threadIdx.x & 31;
    int warp = threadIdx.x >> 5;

    __shared__ float sw[CHUNK];
    __shared__ float4 s0[8][32];   // [warp][lane] -> cols lane*4 .. +3
    __shared__ float4 s1[8][32];   // [warp][lane] -> cols 128+lane*4 .. +3
    if (threadIdx.x < CHUNK) {
        int r = row0 + threadIdx.x;
        sw[threadIdx.x] = __expf(g_logits[r] - g_bmax[b]) * g_binv[b] * gp[r];
    }
    __syncthreads();

    float4 acc0 = make_float4(0.f, 0.f, 0.f, 0.f);
    float4 acc1 = make_float4(0.f, 0.f, 0.f, 0.f);
    int r0 = row0 + warp * 8;
#pragma unroll
    for (int i = 0; i < 8; i++) {
        const float4* rp = reinterpret_cast<const float4*>(ms + (size_t)(r0 + i) * DD);
        float4 a0 = rp[lane];
        float4 a1 = rp[lane + 32];
        float w = sw[warp * 8 + i];
        acc0.x = fmaf(w, a0.x, acc0.x);
        acc0.y = fmaf(w, a0.y, acc0.y);
        acc0.z = fmaf(w, a0.z, acc0.z);
        acc0.w = fmaf(w, a0.w, acc0.w);
        acc1.x = fmaf(w, a1.x, acc1.x);
        acc1.y = fmaf(w, a1.y, acc1.y);
        acc1.z = fmaf(w, a1.z, acc1.z);
        acc1.w = fmaf(w, a1.w, acc1.w);
    }
    s0[warp][lane] = acc0;
    s1[warp][lane] = acc1;
    __syncthreads();

    // 64 threads: thread t<32 sums slot t of s0 (cols t*4), t in [32,64) sums
    // slot t-32 of s1 (cols 128+(t-32)*4). 8-way smem sum + 4 atomics each.
    if (threadIdx.x < 64) {
        int half = threadIdx.x >> 5;          // 0 -> s0, 1 -> s1
        int slot = threadIdx.x & 31;
        float4 r = half ? s1[0][slot] : s0[0][slot];
#pragma unroll
        for (int w = 1; w < 8; w++) {
            float4 v = half ? s1[w][slot] : s0[w][slot];
            r.x += v.x; r.y += v.y; r.z += v.z; r.w += v.w;
        }
        float* o = g_o + b * DD + half * 128 + slot * 4;
        atomicAdd(o + 0, r.x);
        atomicAdd(o + 1, r.y);
        atomicAdd(o + 2, r.z);
        atomicAdd(o + 3, r.w);
    }
}

// ---------------------------------------------------------------------------
// K4 (last hop only): prob_soft = softmax(logits), massively parallel
// ---------------------------------------------------------------------------
__global__ void k_prob(float* __restrict__ out_prob) {
    int i = blockIdx.x * 256 + threadIdx.x;    // 256 blocks x 256 = 65536
    int b = i >> 13;
    out_prob[i] = __expf(g_logits[i] - g_bmax[b]) * g_binv[b];
}

// ---------------------------------------------------------------------------
extern "C" void kernel_launch(void* const* d_in, const int* in_sizes, int n_in,
                              void* d_out, int out_size) {
    const float* q  = (const float*)d_in[0];   // (8,256)
    const float* gp = (const float*)d_in[1];   // (8,8192)
    const float* ms = (const float*)d_in[2];   // (4,8,8192,256)

    float* out        = (float*)d_out;
    float* out_prob   = out;                   // prob_soft  : first  B*M
    float* out_logits = out + BB * MM;         // prob_logits: second B*M

    const size_t SLICE = (size_t)BB * MM * DD;

    k_init<<<8, 256>>>();

    for (int h = 0; h < HOPS; h++) {
        bool last = (h == HOPS - 1);
        k_logits<<<BB * MM / 64, 256>>>(ms + (size_t)h * SLICE, q, gp,
                                        last ? out_logits : nullptr);
        k_combine<<<1, 256>>>();
        if (!last) {
            // Slice h+1 is read here and again by the next k_logits while it
            // may still be L2-resident — keep this ordering.
            k_ok<<<BB * MM / 64, 256>>>(ms + (size_t)(h + 1) * SLICE, gp);
        } else {
            k_prob<<<BB * MM / 256, 256>>>(out_prob);
        }
    }
}

// round 10
// speedup vs baseline: 1.1024x; 1.1024x over previous
#include <cuda_runtime.h>
#include <cstddef>

#define BB 8
#define MM 8192
#define DD 256
#define HOPS 3

// Scratch (allocation-free __device__ globals)
__device__ float g_o[BB * DD];        // cumulative sum of o_k across hops (u = q + g_o)
__device__ float g_logits[BB * MM];
__device__ float g_pmax[BB * 128];    // per-block softmax partial max   (128 blocks per b)
__device__ float g_psum[BB * 128];    // per-block partial sum of exp(l - pmax)
__device__ float g_bmax[BB];
__device__ float g_binv[BB];          // 1 / sum_exp

// ---------------------------------------------------------------------------
// K0: zero the cumulative o accumulator
// ---------------------------------------------------------------------------
__global__ void k_init() {
    g_o[blockIdx.x * 256 + threadIdx.x] = 0.0f;   // 8 blocks x 256
}

// ---------------------------------------------------------------------------
// K1: logits[b,m] = gp[b,m] * dot(ms[b,m,:], q[b,:] + g_o[b,:])
//     + per-block softmax stats (max, sum-exp) into g_pmax/g_psum.
// warp-per-row, 8 independent rows per warp, float4 loads. Measured ~6 TB/s.
// ---------------------------------------------------------------------------
__global__ void __launch_bounds__(256)
k_logits(const float* __restrict__ ms,
         const float* __restrict__ q,
         const float* __restrict__ gp,
         float* __restrict__ out_logits /* null unless last hop */) {
    const int ROWS = 64;
    int row0 = blockIdx.x * ROWS;
    int b = row0 >> 13;                    // / 8192 ; 64 | 8192 -> no straddle
    int lane = threadIdx.x & 31;
    int warp = threadIdx.x >> 5;

    __shared__ float su[DD];
    __shared__ float srow[ROWS];
    su[threadIdx.x] = q[b * DD + threadIdx.x] + g_o[b * DD + threadIdx.x];
    __syncthreads();

    float4 ub0 = reinterpret_cast<const float4*>(su)[lane];
    float4 ub1 = reinterpret_cast<const float4*>(su)[lane + 32];

    int r0 = row0 + warp * 8;
#pragma unroll
    for (int i = 0; i < 8; i++) {
        int row = r0 + i;
        const float4* rp = reinterpret_cast<const float4*>(ms + (size_t)row * DD);
        float4 a0 = rp[lane];
        float4 a1 = rp[lane + 32];
        float s = a0.x * ub0.x + a0.y * ub0.y + a0.z * ub0.z + a0.w * ub0.w
                + a1.x * ub1.x + a1.y * ub1.y + a1.z * ub1.z + a1.w * ub1.w;
#pragma unroll
        for (int off = 16; off; off >>= 1)
            s += __shfl_xor_sync(0xffffffffu, s, off);
        if (lane == 0) {
            float v = s * gp[row];
            g_logits[row] = v;
            srow[warp * 8 + i] = v;
            if (out_logits) out_logits[row] = v;
        }
    }
    __syncthreads();

    // Block-local softmax stats over the 64 logits (warp 0 only)
    if (warp == 0) {
        float v0 = srow[lane];
        float v1 = srow[lane + 32];
        float m = fmaxf(v0, v1);
#pragma unroll
        for (int off = 16; off; off >>= 1)
            m = fmaxf(m, __shfl_xor_sync(0xffffffffu, m, off));
        float s = __expf(v0 - m) + __expf(v1 - m);
#pragma unroll
        for (int off = 16; off; off >>= 1)
            s += __shfl_xor_sync(0xffffffffu, s, off);
        if (lane == 0) {
            g_pmax[blockIdx.x] = m;    // blocks within b are contiguous
            g_psum[blockIdx.x] = s;
        }
    }
}

// ---------------------------------------------------------------------------
// K2: merge 128 partial (max,sum) pairs per b -> (bmax, 1/sum). 1 CTA, 8 warps.
// ---------------------------------------------------------------------------
__global__ void k_combine() {
    int b = threadIdx.x >> 5;
    int lane = threadIdx.x & 31;
    float m = -1e30f, s = 0.0f;
#pragma unroll
    for (int i = 0; i < 4; i++) {
        int idx = b * 128 + i * 32 + lane;
        float pm = g_pmax[idx], ps = g_psum[idx];
        float nm = fmaxf(m, pm);
        s = s * __expf(m - nm) + ps * __expf(pm - nm);
        m = nm;
    }
#pragma unroll
    for (int off = 16; off; off >>= 1) {
        float om = __shfl_xor_sync(0xffffffffu, m, off);
        float os = __shfl_xor_sync(0xffffffffu, s, off);
        float nm = fmaxf(m, om);
        s = s * __expf(m - nm) + os * __expf(om - nm);
        m = nm;
    }
    if (lane == 0) {
        g_bmax[b] = m;
        g_binv[b] = 1.0f / s;
    }
}

// ---------------------------------------------------------------------------
// K3: o[b,:] += sum_m softmax(l)[m] * gp[m] * ms[b,m,:]
// R8 structure (measured best) + forced MLP: loads batched 4-at-a-time into
// registers before FMAs, two alternating accumulators to break the fma chain.
// Light epilogue: sred smem + 64-thread atomic finish (R8's, measured good).
// ---------------------------------------------------------------------------
__global__ void __launch_bounds__(256)
k_ok(const float* __restrict__ ms, const float* __restrict__ gp) {
    const int CHUNK = 64;
    int row0 = blockIdx.x * CHUNK;
    int b = row0 >> 13;
    int c = threadIdx.x & 63;              // float4 column 0..63
    int g = threadIdx.x >> 6;              // row group 0..3

    __shared__ float sw[CHUNK];
    __shared__ float4 sred[4][64];
    if (threadIdx.x < CHUNK) {
        int r = row0 + threadIdx.x;
        sw[threadIdx.x] = __expf(g_logits[r] - g_bmax[b]) * g_binv[b] * gp[r];
    }
    __syncthreads();

    const float* base = ms + (size_t)row0 * DD;
    float4 acc0 = make_float4(0.f, 0.f, 0.f, 0.f);
    float4 acc1 = make_float4(0.f, 0.f, 0.f, 0.f);
#pragma unroll
    for (int k = 0; k < 4; k++) {
        int m0 = g + k * 16;               // rows m0, m0+4, m0+8, m0+12
        // Batch 4 independent loads first (forces >=4 LDG.128 in flight)
        float4 a0 = reinterpret_cast<const float4*>(base + (size_t)(m0     ) * DD)[c];
        float4 a1 = reinterpret_cast<const float4*>(base + (size_t)(m0 +  4) * DD)[c];
        float4 a2 = reinterpret_cast<const float4*>(base + (size_t)(m0 +  8) * DD)[c];
        float4 a3 = reinterpret_cast<const float4*>(base + (size_t)(m0 + 12) * DD)[c];
        float w0 = sw[m0], w1 = sw[m0 + 4], w2 = sw[m0 + 8], w3 = sw[m0 + 12];
        acc0.x = fmaf(w0, a0.x, acc0.x); acc1.x = fmaf(w1, a1.x, acc1.x);
        acc0.y = fmaf(w0, a0.y, acc0.y); acc1.y = fmaf(w1, a1.y, acc1.y);
        acc0.z = fmaf(w0, a0.z, acc0.z); acc1.z = fmaf(w1, a1.z, acc1.z);
        acc0.w = fmaf(w0, a0.w, acc0.w); acc1.w = fmaf(w1, a1.w, acc1.w);
        acc0.x = fmaf(w2, a2.x, acc0.x); acc1.x = fmaf(w3, a3.x, acc1.x);
        acc0.y = fmaf(w2, a2.y, acc0.y); acc1.y = fmaf(w3, a3.y, acc1.y);
        acc0.z = fmaf(w2, a2.z, acc0.z); acc1.z = fmaf(w3, a3.z, acc1.z);
        acc0.w = fmaf(w2, a2.w, acc0.w); acc1.w = fmaf(w3, a3.w, acc1.w);
    }
    acc0.x += acc1.x; acc0.y += acc1.y; acc0.z += acc1.z; acc0.w += acc1.w;
    sred[g][c] = acc0;
    __syncthreads();

    if (g == 0) {
        float4 r0 = sred[0][c], r1 = sred[1][c], r2 = sred[2][c], r3 = sred[3][c];
        float* o = g_o + b * DD + c * 4;
        atomicAdd(o + 0, r0.x + r1.x + r2.x + r3.x);
        atomicAdd(o + 1, r0.y + r1.y + r2.y + r3.y);
        atomicAdd(o + 2, r0.z + r1.z + r2.z + r3.z);
        atomicAdd(o + 3, r0.w + r1.w + r2.w + r3.w);
    }
}

// ---------------------------------------------------------------------------
// K4 (last hop only): prob_soft = softmax(logits), massively parallel
// ---------------------------------------------------------------------------
__global__ void k_prob(float* __restrict__ out_prob) {
    int i = blockIdx.x * 256 + threadIdx.x;    // 256 blocks x 256 = 65536
    int b = i >> 13;
    out_prob[i] = __expf(g_logits[i] - g_bmax[b]) * g_binv[b];
}

// ---------------------------------------------------------------------------
extern "C" void kernel_launch(void* const* d_in, const int* in_sizes, int n_in,
                              void* d_out, int out_size) {
    const float* q  = (const float*)d_in[0];   // (8,256)
    const float* gp = (const float*)d_in[1];   // (8,8192)
    const float* ms = (const float*)d_in[2];   // (4,8,8192,256)

    float* out        = (float*)d_out;
    float* out_prob   = out;                   // prob_soft  : first  B*M
    float* out_logits = out + BB * MM;         // prob_logits: second B*M

    const size_t SLICE = (size_t)BB * MM * DD;

    k_init<<<8, 256>>>();

    for (int h = 0; h < HOPS; h++) {
        bool last = (h == HOPS - 1);
        k_logits<<<BB * MM / 64, 256>>>(ms + (size_t)h * SLICE, q, gp,
                                        last ? out_logits : nullptr);
        k_combine<<<1, 256>>>();
        if (!last) {
            // Slice h+1 is read here and again by the next k_logits while it
            // may still be L2-resident — keep this ordering.
            k_ok<<<BB * MM / 64, 256>>>(ms + (size_t)(h + 1) * SLICE, gp);
        } else {
            k_prob<<<BB * MM / 256, 256>>>(out_prob);
        }
    }
}